// round 14
// baseline (speedup 1.0000x reference)
#include <cuda_runtime.h>
#include <cuda_fp16.h>
#include <math.h>
#include <stdint.h>

#define NB 32
#define NT 3136
#define DIM 384
#define NH 8
#define CH 48
#define EPS 1e-12f

// ---------------- scratch (__device__ globals; allocation-free rule) --------
// fp16 hi/lo splits (22-bit combined mantissa). g_xh/g_xl padded 64 rows for
// the final GEMM's 128-wide token tiles (3136 = 24.5*128).
__device__ __align__(256) __half g_xh[(size_t)NB*NT*DIM + 64*DIM];
__device__ __align__(256) __half g_xl[(size_t)NB*NT*DIM + 64*DIM];
__device__ __align__(256) __half g_xth[(size_t)NB*DIM*NT];  // x^T (b,d,n)
__device__ __align__(256) __half g_xtl[(size_t)NB*DIM*NT];
__device__ __align__(256) __half g_wqh[3*DIM*DIM];
__device__ __align__(256) __half g_wql[3*DIM*DIM];
__device__ __align__(256) __half g_pwh[DIM*DIM];
__device__ __align__(256) __half g_pwl[DIM*DIM];
__device__ __align__(256) float g_Gbig[64*DIM*DIM];         // K-split halves
__device__ __align__(256) __half g_Gh[NB*DIM*DIM];
__device__ __align__(256) __half g_Gl[NB*DIM*DIM];
__device__ __align__(256) float g_tu[(size_t)NB*2*DIM*DIM]; // T(0:384) U(384:768)
__device__ __align__(256) __half g_mth[NB*DIM*DIM];         // M^T (b,d',d)
__device__ __align__(256) __half g_mtl[NB*DIM*DIM];
__device__ __align__(256) __half g_rh[NB*DIM*DIM];          // R (b,e,d')
__device__ __align__(256) __half g_rl[NB*DIM*DIM];

// ---------------------------------------------------------------------------
static __device__ __forceinline__ uint32_t sptr(const void* p) {
    return (uint32_t)__cvta_generic_to_shared(p);
}
static __device__ __forceinline__ uint32_t pkh(__half a, __half b) {
    uint16_t ua = *reinterpret_cast<uint16_t*>(&a);
    uint16_t ub = *reinterpret_cast<uint16_t*>(&b);
    return (uint32_t)ua | ((uint32_t)ub << 16);
}
static __device__ __forceinline__ void cp16(uint32_t s, const void* g) {
    asm volatile("cp.async.cg.shared.global [%0], [%1], 16;\n" :: "r"(s), "l"(g));
}
static __device__ __forceinline__ void ldsm4(uint32_t* r, uint32_t a) {
    asm volatile("ldmatrix.sync.aligned.m8n8.x4.shared.b16 {%0,%1,%2,%3}, [%4];"
                 : "=r"(r[0]), "=r"(r[1]), "=r"(r[2]), "=r"(r[3]) : "r"(a));
}
// hh product: fp16 operands, fp32 accumulator (precision-critical path)
static __device__ __forceinline__ void mma_f32(float* c, const uint32_t* a,
                                               uint32_t b0, uint32_t b1) {
    asm volatile(
        "mma.sync.aligned.m16n8k16.row.col.f32.f16.f16.f32 "
        "{%0,%1,%2,%3}, {%4,%5,%6,%7}, {%8,%9}, {%0,%1,%2,%3};"
        : "+f"(c[0]), "+f"(c[1]), "+f"(c[2]), "+f"(c[3])
        : "r"(a[0]), "r"(a[1]), "r"(a[2]), "r"(a[3]), "r"(b0), "r"(b1));
}
// correction products: fp16 accumulator (2x rate on f16-acc pipe)
static __device__ __forceinline__ void mma_f16(uint32_t* c, const uint32_t* a,
                                               uint32_t b0, uint32_t b1) {
    asm volatile(
        "mma.sync.aligned.m16n8k16.row.col.f16.f16.f16.f16 "
        "{%0,%1}, {%2,%3,%4,%5}, {%6,%7}, {%0,%1};"
        : "+r"(c[0]), "+r"(c[1])
        : "r"(a[0]), "r"(a[1]), "r"(a[2]), "r"(a[3]), "r"(b0), "r"(b1));
}
static __device__ __forceinline__ void split1(float v, __half& h, __half& l) {
    h = __float2half(v);
    l = __float2half(v - __half2float(h));
}

// ---------------------------------------------------------------------------
// conv_split: fp32 -> (fp16 hi, fp16 lo), 4 elems/thread.
// ---------------------------------------------------------------------------
__global__ __launch_bounds__(256) void conv_split(const float4* __restrict__ src,
                                                  uint2* __restrict__ h,
                                                  uint2* __restrict__ l, int n4) {
    int i = blockIdx.x * 256 + threadIdx.x;
    if (i >= n4) return;
    float4 v = src[i];
    __half h0, h1, h2, h3, l0, l1, l2, l3;
    split1(v.x, h0, l0); split1(v.y, h1, l1);
    split1(v.z, h2, l2); split1(v.w, h3, l3);
    h[i] = make_uint2(pkh(h0, h1), pkh(h2, h3));
    l[i] = make_uint2(pkh(l0, l1), pkh(l2, l3));
}

// sum two G halves and split to fp16 hi/lo
__global__ __launch_bounds__(256) void conv_sum(uint2* __restrict__ h,
                                                uint2* __restrict__ l) {
    const int SLAB4 = DIM * DIM / 4;
    int i = blockIdx.x * 256 + threadIdx.x;
    if (i >= NB * SLAB4) return;
    int b = i / SLAB4, j = i - b * SLAB4;
    const float4* p0 = (const float4*)g_Gbig + (size_t)(2 * b) * SLAB4 + j;
    const float4* p1 = (const float4*)g_Gbig + (size_t)(2 * b + 1) * SLAB4 + j;
    float4 a = *p0, c = *p1;
    float4 v = make_float4(a.x + c.x, a.y + c.y, a.z + c.z, a.w + c.w);
    __half h0, h1, h2, h3, l0, l1, l2, l3;
    split1(v.x, h0, l0); split1(v.y, h1, l1);
    split1(v.z, h2, l2); split1(v.w, h3, l3);
    h[i] = make_uint2(pkh(h0, h1), pkh(h2, h3));
    l[i] = make_uint2(pkh(l0, l1), pkh(l2, l3));
}

// ---------------------------------------------------------------------------
// Fused: x (b,n,d) fp32 -> x hi/lo (b,n,d) AND x^T hi/lo (b,d,n) fp16.
// ---------------------------------------------------------------------------
__global__ __launch_bounds__(256) void transpose_split(const float* __restrict__ x) {
    __shared__ float ts[32][33];
    const int nb = blockIdx.x * 32, db = blockIdx.y * 32, b = blockIdx.z;
    const int tx = threadIdx.x & 31, ty = threadIdx.x >> 5;
    #pragma unroll
    for (int i = 0; i < 4; i++) {
        int n = nb + ty + i * 8;
        float v = x[((size_t)b * NT + n) * DIM + db + tx];
        ts[ty + i * 8][tx] = v;
        __half h, l;
        split1(v, h, l);
        size_t o = ((size_t)b * NT + n) * DIM + db + tx;
        g_xh[o] = h;
        g_xl[o] = l;
    }
    __syncthreads();
    #pragma unroll
    for (int i = 0; i < 4; i++) {
        int d = db + ty + i * 8;
        float v = ts[tx][ty + i * 8];
        __half h, l;
        split1(v, h, l);
        size_t o = ((size_t)b * DIM + d) * NT + nb + tx;
        g_xth[o] = h;
        g_xtl[o] = l;
    }
}

// ---------------------------------------------------------------------------
// HMMA GEMM, fp16 hi/lo split, 3-stage cp.async ring, CTA 128m x 128n,
// warp tile 32m x 64n. Per k-step per tile: hh in f32-acc, (lh + hl) share one
// f16 accumulator -> 32 cyc of MMA issue vs 48 for the all-f32-acc version.
// MODE 0: fp32 C -> outF.   MODE 1: split C -> oH/oL.
// MODE 2: y[token, e] = C[e, token] + bias[e]  (transposed; token guarded)
// KSPLIT 1: blockIdx.z = 2*batch + khalf.
// ---------------------------------------------------------------------------
#define STG   24576           // per stage: Ah 6144 | Al 6144 | Bh 6144 | Bl 6144
#define GSMEM (3 * STG)       // 73728 >= Csm overlay 128*132*4 = 67584

template <int MODE, int KSPLIT>
__global__ __launch_bounds__(256) void gemm5(
    const __half* __restrict__ Ahg, const __half* __restrict__ Alg,
    const __half* __restrict__ Bhg, const __half* __restrict__ Blg,
    int lda, int ldb, size_t sA, size_t sB, int NS, int kHalf,
    float* __restrict__ outF, size_t sC, int ldc,
    __half* __restrict__ oH, __half* __restrict__ oL,
    const float* __restrict__ bias, float* __restrict__ y) {
    extern __shared__ __align__(16) char dsm[];
    float (*Csm)[132] = (float(*)[132])dsm;
    const uint32_t base = sptr(dsm);

    const int tid  = threadIdx.x;
    const int lane = tid & 31;
    const int wid  = tid >> 5;
    const int wm   = (wid & 3) * 32;
    const int we   = (wid >> 2) * 64;
    const int mBase = blockIdx.y * 128;
    const int eBase = blockIdx.x * 128;
    const int z  = blockIdx.z;
    const int bz = KSPLIT ? (z >> 1) : z;
    const int koff = KSPLIT ? (z & 1) * kHalf : 0;

    // ---- producer addressing (4 x cp16 per thread per stage) ----
    const int arow = tid >> 1, achk = (tid & 1) * 8;
    const __half* gAh = Ahg + bz * sA + (size_t)(mBase + arow) * lda + koff + achk;
    const __half* gAl = Alg + bz * sA + (size_t)(mBase + arow) * lda + koff + achk;
    const __half* gBh = Bhg + bz * sB + (size_t)(eBase + arow) * ldb + koff + achk;
    const __half* gBl = Blg + bz * sB + (size_t)(eBase + arow) * ldb + koff + achk;
    const uint32_t sAh = base + (uint32_t)(arow * 48 + (tid & 1) * 16);

    // ---- consumer (ldmatrix) addressing ----
    const int rA  = (lane & 7) + ((lane >> 3) & 1) * 8;
    const int kxA = (lane >> 4) * 8;
    const int rB  = (lane & 7) + (lane >> 4) * 8;
    const int kxB = ((lane >> 3) & 1) * 8;
    const uint32_t aAh = base + (uint32_t)((wm + rA) * 48 + kxA * 2);
    const uint32_t aAl = aAh + 6144;
    const uint32_t aBh = base + 12288 + (uint32_t)((we + rB) * 48 + kxB * 2);
    const uint32_t aBl = aBh + 6144;
    const uint32_t TOFF = 768;  // 16 rows * 48B

    float acc[2][8][4] = {};
    uint32_t acc16[2][8][2];
    #pragma unroll
    for (int im = 0; im < 2; im++)
        #pragma unroll
        for (int jn = 0; jn < 8; jn++) { acc16[im][jn][0] = 0; acc16[im][jn][1] = 0; }

    auto load_stage = [&](int st, int k0) {
        const uint32_t o = (uint32_t)(st * STG);
        cp16(sAh + o, gAh + k0);
        cp16(sAh + o + 6144, gAl + k0);
        cp16(sAh + o + 12288, gBh + k0);
        cp16(sAh + o + 18432, gBl + k0);
    };

    // prologue: stages 0,1 in flight
    load_stage(0, 0);
    asm volatile("cp.async.commit_group;\n");
    load_stage(1, 16);
    asm volatile("cp.async.commit_group;\n");

    int st = 0;
    for (int s = 0; s < NS; s++) {
        asm volatile("cp.async.wait_group 1;\n");  // stage s ready
        __syncthreads();                           // all warps done with s-1
        if (s + 2 < NS) {
            int nst = st + 2; if (nst >= 3) nst -= 3;
            load_stage(nst, (s + 2) * 16);
        }
        asm volatile("cp.async.commit_group;\n");

        const uint32_t o = (uint32_t)(st * STG);
        uint32_t ah[2][4], al[2][4], bh[4][4], bl[4][4];
        ldsm4(ah[0], aAh + o);        ldsm4(ah[1], aAh + o + TOFF);
        ldsm4(al[0], aAl + o);        ldsm4(al[1], aAl + o + TOFF);
        #pragma unroll
        for (int j = 0; j < 4; j++) {
            ldsm4(bh[j], aBh + o + j * TOFF);
            ldsm4(bl[j], aBl + o + j * TOFF);
        }
        #pragma unroll
        for (int im = 0; im < 2; im++)
            #pragma unroll
            for (int jn = 0; jn < 8; jn++) {
                const int ie = jn >> 1, sub = (jn & 1) * 2;
                mma_f32(acc[im][jn], ah[im], bh[ie][sub], bh[ie][sub + 1]);
                mma_f16(acc16[im][jn], al[im], bh[ie][sub], bh[ie][sub + 1]);
                mma_f16(acc16[im][jn], ah[im], bl[ie][sub], bl[ie][sub + 1]);
            }
        if (++st == 3) st = 0;
    }

    // ---- combine f16 corrections into fp32, stage C through smem ----
    __syncthreads();
    const int rr = lane >> 2, cq = (lane & 3) * 2;
    #pragma unroll
    for (int im = 0; im < 2; im++)
        #pragma unroll
        for (int jn = 0; jn < 8; jn++) {
            const __half2 p0 = *reinterpret_cast<const __half2*>(&acc16[im][jn][0]);
            const __half2 p1 = *reinterpret_cast<const __half2*>(&acc16[im][jn][1]);
            const float c0 = acc[im][jn][0] + __low2float(p0);
            const float c1 = acc[im][jn][1] + __high2float(p0);
            const float c2 = acc[im][jn][2] + __low2float(p1);
            const float c3 = acc[im][jn][3] + __high2float(p1);
            const int row = wm + im * 16 + rr;
            const int col = we + jn * 8 + cq;
            if (MODE == 2) {  // transposed: Csm[n][e]
                Csm[col][row]         = c0;
                Csm[col + 1][row]     = c1;
                Csm[col][row + 8]     = c2;
                Csm[col + 1][row + 8] = c3;
            } else {
                Csm[row][col]         = c0;
                Csm[row][col + 1]     = c1;
                Csm[row + 8][col]     = c2;
                Csm[row + 8][col + 1] = c3;
            }
        }
    __syncthreads();

    if (MODE == 0) {
        const int r8 = tid >> 5, c4 = (tid & 31) * 4;
        #pragma unroll
        for (int it = 0; it < 16; it++) {
            const int row = it * 8 + r8;
            *(float4*)(outF + (size_t)z * sC + (size_t)(mBase + row) * ldc +
                       eBase + c4) = *(float4*)&Csm[row][c4];
        }
    } else if (MODE == 1) {
        const int r8 = tid >> 5, c4 = (tid & 31) * 4;
        #pragma unroll
        for (int it = 0; it < 16; it++) {
            const int row = it * 8 + r8;
            float4 v = *(float4*)&Csm[row][c4];
            __half h0, h1, h2, h3, l0, l1, l2, l3;
            split1(v.x, h0, l0); split1(v.y, h1, l1);
            split1(v.z, h2, l2); split1(v.w, h3, l3);
            const size_t oo = (size_t)z * sC + (size_t)(mBase + row) * ldc +
                              eBase + c4;
            *(uint2*)(oH + oo) = make_uint2(pkh(h0, h1), pkh(h2, h3));
            *(uint2*)(oL + oo) = make_uint2(pkh(l0, l1), pkh(l2, l3));
        }
    } else {  // MODE 2: y[token, e] = Csm[n][e] + bias[e]
        const int e4 = lane * 4;
        const float4 bv = *(const float4*)(bias + mBase + e4);
        #pragma unroll
        for (int it = 0; it < 16; it++) {
            const int nl = wid + it * 8;
            const int n = eBase + nl;
            if (n < NT) {
                float4 v = *(float4*)&Csm[nl][e4];
                v.x += bv.x; v.y += bv.y; v.z += bv.z; v.w += bv.w;
                *(float4*)(y + ((size_t)bz * NT + n) * DIM + mBase + e4) = v;
            }
        }
    }
}

// ---------------------------------------------------------------------------
// scores: per (b,h) — scores = Wq G Wk^T / (|q||k|) * T, softmax, then
// Mt[d', h*48+c] = sum_{c'} attn[c,c'] * Wv[c', d']  (fp16 hi/lo out).
// ---------------------------------------------------------------------------
__global__ __launch_bounds__(256) void scores_kernel(
    const float* __restrict__ qkv_w, const float* __restrict__ temp) {
    union {
        struct { float TS[48][36], WkS[48][36], US[48][36], WqS[48][36]; } a;
        float WvS[48][68];
    } __shared__ u;
    __shared__ float Sm[48][49];
    __shared__ float iqn[48], ikn[48];

    const int bh = blockIdx.x, b = bh >> 3, h = bh & 7;
    const int tid = threadIdx.x;
    const float* Tb = g_tu + (size_t)b * 2 * DIM * DIM + (h * CH) * DIM;
    const float* Ub = Tb + (size_t)DIM * DIM;
    const float* Wq = qkv_w + (size_t)(h * CH) * DIM;
    const float* Wk = qkv_w + (size_t)(DIM + h * CH) * DIM;
    const float* Wv = qkv_w + (size_t)(2 * DIM + h * CH) * DIM;

    const int c0 = (tid >> 4) * 3;
    const int d0 = (tid & 15) * 3;
    const bool doQ = (d0 == 0);
    const bool doK = (c0 == 0);
    float acc[3][3] = {};
    float nq[3] = {}, nk[3] = {};

    for (int e0 = 0; e0 < DIM; e0 += 32) {
        for (int t = tid; t < 1536; t += 256) {
            const int arr = t / 384, rem = t - arr * 384;
            const int r = rem >> 3, c4 = (rem & 7) * 4;
            const float4 v = (arr == 0)
                ? *(const float4*)(Tb + (size_t)r * DIM + e0 + c4)
                : (arr == 1)
                ? *(const float4*)(Wk + (size_t)r * DIM + e0 + c4)
                : (arr == 2)
                ? *(const float4*)(Ub + (size_t)r * DIM + e0 + c4)
                : *(const float4*)(Wq + (size_t)r * DIM + e0 + c4);
            float* dst = (arr == 0) ? &u.a.TS[r][c4]
                       : (arr == 1) ? &u.a.WkS[r][c4]
                       : (arr == 2) ? &u.a.US[r][c4]
                                    : &u.a.WqS[r][c4];
            *(float4*)dst = v;
        }
        __syncthreads();
        #pragma unroll
        for (int k = 0; k < 32; k++) {
            float a0 = u.a.TS[c0][k], a1 = u.a.TS[c0+1][k], a2 = u.a.TS[c0+2][k];
            float b0 = u.a.WkS[d0][k], b1 = u.a.WkS[d0+1][k], b2 = u.a.WkS[d0+2][k];
            acc[0][0] += a0*b0; acc[0][1] += a0*b1; acc[0][2] += a0*b2;
            acc[1][0] += a1*b0; acc[1][1] += a1*b1; acc[1][2] += a1*b2;
            acc[2][0] += a2*b0; acc[2][1] += a2*b1; acc[2][2] += a2*b2;
            if (doQ) {
                nq[0] += a0 * u.a.WqS[c0][k];
                nq[1] += a1 * u.a.WqS[c0+1][k];
                nq[2] += a2 * u.a.WqS[c0+2][k];
            }
            if (doK) {
                nk[0] += u.a.US[d0][k] * b0;
                nk[1] += u.a.US[d0+1][k] * b1;
                nk[2] += u.a.US[d0+2][k] * b2;
            }
        }
        __syncthreads();
    }

    if (doQ) {
        #pragma unroll
        for (int i = 0; i < 3; i++) iqn[c0+i] = 1.f / fmaxf(sqrtf(nq[i]), EPS);
    }
    if (doK) {
        #pragma unroll
        for (int i = 0; i < 3; i++) ikn[d0+i] = 1.f / fmaxf(sqrtf(nk[i]), EPS);
    }
    __syncthreads();

    const float T = temp[h];
    #pragma unroll
    for (int i = 0; i < 3; i++)
        #pragma unroll
        for (int j = 0; j < 3; j++)
            Sm[c0+i][d0+j] = acc[i][j] * iqn[c0+i] * ikn[d0+j] * T;
    __syncthreads();

    if (tid < 48) {
        float m = -1e30f;
        #pragma unroll 8
        for (int d = 0; d < 48; d++) m = fmaxf(m, Sm[tid][d]);
        float sum = 0.f;
        #pragma unroll 8
        for (int d = 0; d < 48; d++) { float e = expf(Sm[tid][d] - m); Sm[tid][d] = e; sum += e; }
        const float inv = 1.f / sum;
        #pragma unroll 8
        for (int d = 0; d < 48; d++) Sm[tid][d] *= inv;
    }
    __syncthreads();

    const int ci = (tid & 15) * 3;
    const int dq = (tid >> 4) * 4;
    for (int dp = 0; dp < DIM; dp += 64) {
        for (int t = tid; t < 768; t += 256) {
            const int r = t >> 4, c4 = (t & 15) * 4;
            *(float4*)&u.WvS[r][c4] = *(const float4*)(Wv + (size_t)r * DIM + dp + c4);
        }
        __syncthreads();
        float a4[3][4] = {};
        #pragma unroll 4
        for (int cp = 0; cp < 48; cp++) {
            float s0 = Sm[ci][cp], s1 = Sm[ci+1][cp], s2 = Sm[ci+2][cp];
            float w0 = u.WvS[cp][dq], w1 = u.WvS[cp][dq+1];
            float w2 = u.WvS[cp][dq+2], w3 = u.WvS[cp][dq+3];
            a4[0][0] += s0*w0; a4[0][1] += s0*w1; a4[0][2] += s0*w2; a4[0][3] += s0*w3;
            a4[1][0] += s1*w0; a4[1][1] += s1*w1; a4[1][2] += s1*w2; a4[1][3] += s1*w3;
            a4[2][0] += s2*w0; a4[2][1] += s2*w1; a4[2][2] += s2*w2; a4[2][3] += s2*w3;
        }
        #pragma unroll
        for (int j = 0; j < 4; j++) {
            const size_t rowo = ((size_t)b * DIM + dp + dq + j) * DIM + h * CH + ci;
            #pragma unroll
            for (int i = 0; i < 3; i++) {
                __half hh, ll;
                split1(a4[i][j], hh, ll);
                g_mth[rowo + i] = hh;
                g_mtl[rowo + i] = ll;
            }
        }
        __syncthreads();
    }
}

// ---------------------------------------------------------------------------
extern "C" void kernel_launch(void* const* d_in, const int* in_sizes, int n_in,
                              void* d_out, int out_size) {
    const float* x      = (const float*)d_in[0];
    const float* qkv_w  = (const float*)d_in[1];
    const float* temp   = (const float*)d_in[2];
    const float* proj_w = (const float*)d_in[3];
    const float* proj_b = (const float*)d_in[4];
    float* y = (float*)d_out;

    __half *xh, *xl, *xth, *xtl, *wqh, *wql, *pwh, *pwl;
    __half *Gh, *Gl, *mth, *mtl, *rh, *rl;
    float *Gbig, *tu;
    cudaGetSymbolAddress((void**)&xh, g_xh);
    cudaGetSymbolAddress((void**)&xl, g_xl);
    cudaGetSymbolAddress((void**)&xth, g_xth);
    cudaGetSymbolAddress((void**)&xtl, g_xtl);
    cudaGetSymbolAddress((void**)&wqh, g_wqh);
    cudaGetSymbolAddress((void**)&wql, g_wql);
    cudaGetSymbolAddress((void**)&pwh, g_pwh);
    cudaGetSymbolAddress((void**)&pwl, g_pwl);
    cudaGetSymbolAddress((void**)&Gbig, g_Gbig);
    cudaGetSymbolAddress((void**)&Gh, g_Gh);
    cudaGetSymbolAddress((void**)&Gl, g_Gl);
    cudaGetSymbolAddress((void**)&tu, g_tu);
    cudaGetSymbolAddress((void**)&mth, g_mth);
    cudaGetSymbolAddress((void**)&mtl, g_mtl);
    cudaGetSymbolAddress((void**)&rh, g_rh);
    cudaGetSymbolAddress((void**)&rl, g_rl);

    const size_t sX  = (size_t)NT * DIM;
    const size_t sXT = (size_t)DIM * NT;
    const size_t sG  = (size_t)DIM * DIM;

    cudaFuncSetAttribute(gemm5<0, 1>, cudaFuncAttributeMaxDynamicSharedMemorySize,
                         GSMEM);
    cudaFuncSetAttribute(gemm5<0, 0>, cudaFuncAttributeMaxDynamicSharedMemorySize,
                         GSMEM);
    cudaFuncSetAttribute(gemm5<1, 0>, cudaFuncAttributeMaxDynamicSharedMemorySize,
                         GSMEM);
    cudaFuncSetAttribute(gemm5<2, 0>, cudaFuncAttributeMaxDynamicSharedMemorySize,
                         GSMEM);

    // converts (x hi/lo + x^T hi/lo fused into one pass over x)
    transpose_split<<<dim3(NT / 32, DIM / 32, NB), 256>>>(x);
    conv_split<<<432, 256>>>((const float4*)qkv_w, (uint2*)wqh, (uint2*)wql,
                             3 * DIM * DIM / 4);
    conv_split<<<144, 256>>>((const float4*)proj_w, (uint2*)pwh, (uint2*)pwl,
                             DIM * DIM / 4);

    // G = x^T x  (K-split in halves of 1568)
    gemm5<0, 1><<<dim3(3, 3, 64), 256, GSMEM>>>(xth, xtl, xth, xtl,
        NT, NT, sXT, sXT, 98, 1568, Gbig, sG, DIM,
        nullptr, nullptr, nullptr, nullptr);
    conv_sum<<<(NB * DIM * DIM / 4 + 255) / 256, 256>>>((uint2*)Gh, (uint2*)Gl);

    // [T;U] = [Wq;Wk] * G
    gemm5<0, 0><<<dim3(3, 6, 32), 256, GSMEM>>>(wqh, wql, Gh, Gl,
        DIM, DIM, 0, sG, 24, 0, tu, 2 * sG, DIM,
        nullptr, nullptr, nullptr, nullptr);

    // scores + softmax + M^T
    scores_kernel<<<NB * NH, 256>>>(qkv_w, temp);

    // R = P * M  (via B = M^T)
    gemm5<1, 0><<<dim3(3, 3, 32), 256, GSMEM>>>(pwh, pwl, mth, mtl,
        DIM, DIM, 0, sG, 24, 0, nullptr, sG, DIM,
        rh, rl, nullptr, nullptr);

    // y = x R^T + bias  (A = R rows e, B = x rows token; transposed store)
    gemm5<2, 0><<<dim3(25, 3, 32), 256, GSMEM>>>(rh, rl, xh, xl,
        DIM, DIM, sG, sX, 24, 0, nullptr, 0, 0,
        nullptr, nullptr, proj_b, y);
}

// round 16
// speedup vs baseline: 1.3141x; 1.3141x over previous
#include <cuda_runtime.h>
#include <cuda_fp16.h>
#include <math.h>
#include <stdint.h>

#define NB 32
#define NT 3136
#define DIM 384
#define NH 8
#define CH 48
#define EPS 1e-12f

// ---------------- scratch (__device__ globals; allocation-free rule) --------
// fp16 hi/lo splits. g_xh/g_xl padded 64 rows for the final GEMM's 128-wide
// token tiles (3136 = 24.5*128).
__device__ __align__(256) __half g_xh[(size_t)NB*NT*DIM + 64*DIM];
__device__ __align__(256) __half g_xl[(size_t)NB*NT*DIM + 64*DIM];
__device__ __align__(256) __half g_xth[(size_t)NB*DIM*NT];  // x^T (b,d,n)
__device__ __align__(256) __half g_xtl[(size_t)NB*DIM*NT];
__device__ __align__(256) __half g_wqh[3*DIM*DIM];
__device__ __align__(256) __half g_wql[3*DIM*DIM];
__device__ __align__(256) __half g_pwh[DIM*DIM];
__device__ __align__(256) __half g_pwl[DIM*DIM];
__device__ __align__(256) float g_Gbig[64*DIM*DIM];         // K-split halves
__device__ __align__(256) __half g_Gh[NB*DIM*DIM];
__device__ __align__(256) __half g_Gl[NB*DIM*DIM];
__device__ __align__(256) float g_tu[(size_t)NB*2*DIM*DIM]; // T(0:384) U(384:768)
__device__ __align__(256) __half g_mth[NB*DIM*DIM];         // M^T (b,d',d)
__device__ __align__(256) __half g_mtl[NB*DIM*DIM];
__device__ __align__(256) __half g_rh[NB*DIM*DIM];          // R (b,e,d')
__device__ __align__(256) __half g_rl[NB*DIM*DIM];

// ---------------------------------------------------------------------------
static __device__ __forceinline__ uint32_t sptr(const void* p) {
    return (uint32_t)__cvta_generic_to_shared(p);
}
static __device__ __forceinline__ uint32_t pkh(__half a, __half b) {
    uint16_t ua = *reinterpret_cast<uint16_t*>(&a);
    uint16_t ub = *reinterpret_cast<uint16_t*>(&b);
    return (uint32_t)ua | ((uint32_t)ub << 16);
}
static __device__ __forceinline__ void cp16(uint32_t s, const void* g) {
    asm volatile("cp.async.cg.shared.global [%0], [%1], 16;\n" :: "r"(s), "l"(g));
}
static __device__ __forceinline__ void ldsm4(uint32_t* r, uint32_t a) {
    asm volatile("ldmatrix.sync.aligned.m8n8.x4.shared.b16 {%0,%1,%2,%3}, [%4];"
                 : "=r"(r[0]), "=r"(r[1]), "=r"(r[2]), "=r"(r[3]) : "r"(a));
}
static __device__ __forceinline__ void mma_f32(float* c, const uint32_t* a,
                                               uint32_t b0, uint32_t b1) {
    asm volatile(
        "mma.sync.aligned.m16n8k16.row.col.f32.f16.f16.f32 "
        "{%0,%1,%2,%3}, {%4,%5,%6,%7}, {%8,%9}, {%0,%1,%2,%3};"
        : "+f"(c[0]), "+f"(c[1]), "+f"(c[2]), "+f"(c[3])
        : "r"(a[0]), "r"(a[1]), "r"(a[2]), "r"(a[3]), "r"(b0), "r"(b1));
}
static __device__ __forceinline__ void split1(float v, __half& h, __half& l) {
    h = __float2half(v);
    l = __float2half(v - __half2float(h));
}

// ---------------------------------------------------------------------------
// conv_split: fp32 -> (fp16 hi, fp16 lo), 4 elems/thread.
// ---------------------------------------------------------------------------
__global__ __launch_bounds__(256) void conv_split(const float4* __restrict__ src,
                                                  uint2* __restrict__ h,
                                                  uint2* __restrict__ l, int n4) {
    int i = blockIdx.x * 256 + threadIdx.x;
    if (i >= n4) return;
    float4 v = src[i];
    __half h0, h1, h2, h3, l0, l1, l2, l3;
    split1(v.x, h0, l0); split1(v.y, h1, l1);
    split1(v.z, h2, l2); split1(v.w, h3, l3);
    h[i] = make_uint2(pkh(h0, h1), pkh(h2, h3));
    l[i] = make_uint2(pkh(l0, l1), pkh(l2, l3));
}

// sum two G halves and split to fp16 hi/lo
__global__ __launch_bounds__(256) void conv_sum(uint2* __restrict__ h,
                                                uint2* __restrict__ l) {
    const int SLAB4 = DIM * DIM / 4;
    int i = blockIdx.x * 256 + threadIdx.x;
    if (i >= NB * SLAB4) return;
    int b = i / SLAB4, j = i - b * SLAB4;
    const float4* p0 = (const float4*)g_Gbig + (size_t)(2 * b) * SLAB4 + j;
    const float4* p1 = (const float4*)g_Gbig + (size_t)(2 * b + 1) * SLAB4 + j;
    float4 a = *p0, c = *p1;
    float4 v = make_float4(a.x + c.x, a.y + c.y, a.z + c.z, a.w + c.w);
    __half h0, h1, h2, h3, l0, l1, l2, l3;
    split1(v.x, h0, l0); split1(v.y, h1, l1);
    split1(v.z, h2, l2); split1(v.w, h3, l3);
    h[i] = make_uint2(pkh(h0, h1), pkh(h2, h3));
    l[i] = make_uint2(pkh(l0, l1), pkh(l2, l3));
}

// ---------------------------------------------------------------------------
// Fused: x (b,n,d) fp32 -> x hi/lo (b,n,d) AND x^T hi/lo (b,d,n) fp16.
// ---------------------------------------------------------------------------
__global__ __launch_bounds__(256) void transpose_split(const float* __restrict__ x) {
    __shared__ float ts[32][33];
    const int nb = blockIdx.x * 32, db = blockIdx.y * 32, b = blockIdx.z;
    const int tx = threadIdx.x & 31, ty = threadIdx.x >> 5;
    #pragma unroll
    for (int i = 0; i < 4; i++) {
        int n = nb + ty + i * 8;
        float v = x[((size_t)b * NT + n) * DIM + db + tx];
        ts[ty + i * 8][tx] = v;
        __half h, l;
        split1(v, h, l);
        size_t o = ((size_t)b * NT + n) * DIM + db + tx;
        g_xh[o] = h;
        g_xl[o] = l;
    }
    __syncthreads();
    #pragma unroll
    for (int i = 0; i < 4; i++) {
        int d = db + ty + i * 8;
        float v = ts[tx][ty + i * 8];
        __half h, l;
        split1(v, h, l);
        size_t o = ((size_t)b * DIM + d) * NT + nb + tx;
        g_xth[o] = h;
        g_xtl[o] = l;
    }
}

// ---------------------------------------------------------------------------
// HMMA GEMM, fp16 2-term split (hh + lh, both f32-acc), 3-stage cp.async ring,
// CTA 128m x 128n, warp tile 32m x 64n. 32 MMA instr / k-step / warp.
// MODE 0: fp32 C -> outF.   MODE 1: split C -> oH/oL.
// MODE 2: y[token, e] = C[e, token] + bias[e]  (transposed; token guarded)
// KSPLIT 1: blockIdx.z = 2*batch + khalf.
// ---------------------------------------------------------------------------
#define STG   24576           // per stage: Ah 6144 | Al 6144 | Bh 6144 | Bl 6144
#define GSMEM (3 * STG)       // 73728 >= Csm overlay 128*132*4 = 67584

template <int MODE, int KSPLIT>
__global__ __launch_bounds__(256) void gemm5(
    const __half* __restrict__ Ahg, const __half* __restrict__ Alg,
    const __half* __restrict__ Bhg, const __half* __restrict__ Blg,
    int lda, int ldb, size_t sA, size_t sB, int NS, int kHalf,
    float* __restrict__ outF, size_t sC, int ldc,
    __half* __restrict__ oH, __half* __restrict__ oL,
    const float* __restrict__ bias, float* __restrict__ y) {
    extern __shared__ __align__(16) char dsm[];
    float (*Csm)[132] = (float(*)[132])dsm;
    const uint32_t base = sptr(dsm);

    const int tid  = threadIdx.x;
    const int lane = tid & 31;
    const int wid  = tid >> 5;
    const int wm   = (wid & 3) * 32;
    const int we   = (wid >> 2) * 64;
    const int mBase = blockIdx.y * 128;
    const int eBase = blockIdx.x * 128;
    const int z  = blockIdx.z;
    const int bz = KSPLIT ? (z >> 1) : z;
    const int koff = KSPLIT ? (z & 1) * kHalf : 0;

    // ---- producer addressing (4 x cp16 per thread per stage) ----
    const int arow = tid >> 1, achk = (tid & 1) * 8;
    const __half* gAh = Ahg + bz * sA + (size_t)(mBase + arow) * lda + koff + achk;
    const __half* gAl = Alg + bz * sA + (size_t)(mBase + arow) * lda + koff + achk;
    const __half* gBh = Bhg + bz * sB + (size_t)(eBase + arow) * ldb + koff + achk;
    const __half* gBl = Blg + bz * sB + (size_t)(eBase + arow) * ldb + koff + achk;
    const uint32_t sAh = base + (uint32_t)(arow * 48 + (tid & 1) * 16);

    // ---- consumer (ldmatrix) addressing ----
    const int rA  = (lane & 7) + ((lane >> 3) & 1) * 8;
    const int kxA = (lane >> 4) * 8;
    const int rB  = (lane & 7) + (lane >> 4) * 8;
    const int kxB = ((lane >> 3) & 1) * 8;
    const uint32_t aAh = base + (uint32_t)((wm + rA) * 48 + kxA * 2);
    const uint32_t aAl = aAh + 6144;
    const uint32_t aBh = base + 12288 + (uint32_t)((we + rB) * 48 + kxB * 2);
    const uint32_t aBl = aBh + 6144;
    const uint32_t TOFF = 768;  // 16 rows * 48B

    float acc[2][8][4] = {};

    auto load_stage = [&](int st, int k0) {
        const uint32_t o = (uint32_t)(st * STG);
        cp16(sAh + o, gAh + k0);
        cp16(sAh + o + 6144, gAl + k0);
        cp16(sAh + o + 12288, gBh + k0);
        cp16(sAh + o + 18432, gBl + k0);
    };

    // prologue: stages 0,1 in flight
    load_stage(0, 0);
    asm volatile("cp.async.commit_group;\n");
    load_stage(1, 16);
    asm volatile("cp.async.commit_group;\n");

    int st = 0;
    for (int s = 0; s < NS; s++) {
        asm volatile("cp.async.wait_group 1;\n");  // stage s ready
        __syncthreads();                           // all warps done with s-1
        if (s + 2 < NS) {
            int nst = st + 2; if (nst >= 3) nst -= 3;
            load_stage(nst, (s + 2) * 16);
        }
        asm volatile("cp.async.commit_group;\n");

        const uint32_t o = (uint32_t)(st * STG);
        uint32_t ah[2][4], al[2][4], bh[4][4];
        ldsm4(ah[0], aAh + o);        ldsm4(ah[1], aAh + o + TOFF);
        ldsm4(al[0], aAl + o);        ldsm4(al[1], aAl + o + TOFF);
        #pragma unroll
        for (int j = 0; j < 4; j++) ldsm4(bh[j], aBh + o + j * TOFF);
        #pragma unroll
        for (int im = 0; im < 2; im++)
            #pragma unroll
            for (int jn = 0; jn < 8; jn++) {
                const int ie = jn >> 1, sub = (jn & 1) * 2;
                mma_f32(acc[im][jn], ah[im], bh[ie][sub], bh[ie][sub + 1]);
                mma_f32(acc[im][jn], al[im], bh[ie][sub], bh[ie][sub + 1]);
            }
        if (++st == 3) st = 0;
    }
    (void)aAl; (void)aBl; (void)gAl; (void)gBl;

    // ---- stage C through smem (overlays the ring; barrier first) ----
    __syncthreads();
    const int rr = lane >> 2, cq = (lane & 3) * 2;
    #pragma unroll
    for (int im = 0; im < 2; im++)
        #pragma unroll
        for (int jn = 0; jn < 8; jn++) {
            const int row = wm + im * 16 + rr;
            const int col = we + jn * 8 + cq;
            if (MODE == 2) {  // transposed: Csm[n][e]
                Csm[col][row]         = acc[im][jn][0];
                Csm[col + 1][row]     = acc[im][jn][1];
                Csm[col][row + 8]     = acc[im][jn][2];
                Csm[col + 1][row + 8] = acc[im][jn][3];
            } else {
                Csm[row][col]         = acc[im][jn][0];
                Csm[row][col + 1]     = acc[im][jn][1];
                Csm[row + 8][col]     = acc[im][jn][2];
                Csm[row + 8][col + 1] = acc[im][jn][3];
            }
        }
    __syncthreads();

    if (MODE == 0) {
        const int r8 = tid >> 5, c4 = (tid & 31) * 4;
        #pragma unroll
        for (int it = 0; it < 16; it++) {
            const int row = it * 8 + r8;
            *(float4*)(outF + (size_t)z * sC + (size_t)(mBase + row) * ldc +
                       eBase + c4) = *(float4*)&Csm[row][c4];
        }
    } else if (MODE == 1) {
        const int r8 = tid >> 5, c4 = (tid & 31) * 4;
        #pragma unroll
        for (int it = 0; it < 16; it++) {
            const int row = it * 8 + r8;
            float4 v = *(float4*)&Csm[row][c4];
            __half h0, h1, h2, h3, l0, l1, l2, l3;
            split1(v.x, h0, l0); split1(v.y, h1, l1);
            split1(v.z, h2, l2); split1(v.w, h3, l3);
            const size_t oo = (size_t)z * sC + (size_t)(mBase + row) * ldc +
                              eBase + c4;
            *(uint2*)(oH + oo) = make_uint2(pkh(h0, h1), pkh(h2, h3));
            *(uint2*)(oL + oo) = make_uint2(pkh(l0, l1), pkh(l2, l3));
        }
    } else {  // MODE 2: y[token, e] = Csm[n][e] + bias[e]
        const int e4 = lane * 4;
        const float4 bv = *(const float4*)(bias + mBase + e4);
        #pragma unroll
        for (int it = 0; it < 16; it++) {
            const int nl = wid + it * 8;
            const int n = eBase + nl;
            if (n < NT) {
                float4 v = *(float4*)&Csm[nl][e4];
                v.x += bv.x; v.y += bv.y; v.z += bv.z; v.w += bv.w;
                *(float4*)(y + ((size_t)bz * NT + n) * DIM + mBase + e4) = v;
            }
        }
    }
}

// ---------------------------------------------------------------------------
// scores: per (b,h) — scores = Wq G Wk^T / (|q||k|) * T, softmax, then
// Mt[d', h*48+c] = sum_{c'} attn[c,c'] * Wv[c', d']  (fp16 hi/lo out).
// ---------------------------------------------------------------------------
__global__ __launch_bounds__(256) void scores_kernel(
    const float* __restrict__ qkv_w, const float* __restrict__ temp) {
    union {
        struct { float TS[48][36], WkS[48][36], US[48][36], WqS[48][36]; } a;
        float WvS[48][68];
    } __shared__ u;
    __shared__ float Sm[48][49];
    __shared__ float iqn[48], ikn[48];

    const int bh = blockIdx.x, b = bh >> 3, h = bh & 7;
    const int tid = threadIdx.x;
    const float* Tb = g_tu + (size_t)b * 2 * DIM * DIM + (h * CH) * DIM;
    const float* Ub = Tb + (size_t)DIM * DIM;
    const float* Wq = qkv_w + (size_t)(h * CH) * DIM;
    const float* Wk = qkv_w + (size_t)(DIM + h * CH) * DIM;
    const float* Wv = qkv_w + (size_t)(2 * DIM + h * CH) * DIM;

    const int c0 = (tid >> 4) * 3;
    const int d0 = (tid & 15) * 3;
    const bool doQ = (d0 == 0);
    const bool doK = (c0 == 0);
    float acc[3][3] = {};
    float nq[3] = {}, nk[3] = {};

    for (int e0 = 0; e0 < DIM; e0 += 32) {
        for (int t = tid; t < 1536; t += 256) {
            const int arr = t / 384, rem = t - arr * 384;
            const int r = rem >> 3, c4 = (rem & 7) * 4;
            const float4 v = (arr == 0)
                ? *(const float4*)(Tb + (size_t)r * DIM + e0 + c4)
                : (arr == 1)
                ? *(const float4*)(Wk + (size_t)r * DIM + e0 + c4)
                : (arr == 2)
                ? *(const float4*)(Ub + (size_t)r * DIM + e0 + c4)
                : *(const float4*)(Wq + (size_t)r * DIM + e0 + c4);
            float* dst = (arr == 0) ? &u.a.TS[r][c4]
                       : (arr == 1) ? &u.a.WkS[r][c4]
                       : (arr == 2) ? &u.a.US[r][c4]
                                    : &u.a.WqS[r][c4];
            *(float4*)dst = v;
        }
        __syncthreads();
        #pragma unroll
        for (int k = 0; k < 32; k++) {
            float a0 = u.a.TS[c0][k], a1 = u.a.TS[c0+1][k], a2 = u.a.TS[c0+2][k];
            float b0 = u.a.WkS[d0][k], b1 = u.a.WkS[d0+1][k], b2 = u.a.WkS[d0+2][k];
            acc[0][0] += a0*b0; acc[0][1] += a0*b1; acc[0][2] += a0*b2;
            acc[1][0] += a1*b0; acc[1][1] += a1*b1; acc[1][2] += a1*b2;
            acc[2][0] += a2*b0; acc[2][1] += a2*b1; acc[2][2] += a2*b2;
            if (doQ) {
                nq[0] += a0 * u.a.WqS[c0][k];
                nq[1] += a1 * u.a.WqS[c0+1][k];
                nq[2] += a2 * u.a.WqS[c0+2][k];
            }
            if (doK) {
                nk[0] += u.a.US[d0][k] * b0;
                nk[1] += u.a.US[d0+1][k] * b1;
                nk[2] += u.a.US[d0+2][k] * b2;
            }
        }
        __syncthreads();
    }

    if (doQ) {
        #pragma unroll
        for (int i = 0; i < 3; i++) iqn[c0+i] = 1.f / fmaxf(sqrtf(nq[i]), EPS);
    }
    if (doK) {
        #pragma unroll
        for (int i = 0; i < 3; i++) ikn[d0+i] = 1.f / fmaxf(sqrtf(nk[i]), EPS);
    }
    __syncthreads();

    const float T = temp[h];
    #pragma unroll
    for (int i = 0; i < 3; i++)
        #pragma unroll
        for (int j = 0; j < 3; j++)
            Sm[c0+i][d0+j] = acc[i][j] * iqn[c0+i] * ikn[d0+j] * T;
    __syncthreads();

    if (tid < 48) {
        float m = -1e30f;
        #pragma unroll 8
        for (int d = 0; d < 48; d++) m = fmaxf(m, Sm[tid][d]);
        float sum = 0.f;
        #pragma unroll 8
        for (int d = 0; d < 48; d++) { float e = expf(Sm[tid][d] - m); Sm[tid][d] = e; sum += e; }
        const float inv = 1.f / sum;
        #pragma unroll 8
        for (int d = 0; d < 48; d++) Sm[tid][d] *= inv;
    }
    __syncthreads();

    const int ci = (tid & 15) * 3;
    const int dq = (tid >> 4) * 4;
    for (int dp = 0; dp < DIM; dp += 64) {
        for (int t = tid; t < 768; t += 256) {
            const int r = t >> 4, c4 = (t & 15) * 4;
            *(float4*)&u.WvS[r][c4] = *(const float4*)(Wv + (size_t)r * DIM + dp + c4);
        }
        __syncthreads();
        float a4[3][4] = {};
        #pragma unroll 4
        for (int cp = 0; cp < 48; cp++) {
            float s0 = Sm[ci][cp], s1 = Sm[ci+1][cp], s2 = Sm[ci+2][cp];
            float w0 = u.WvS[cp][dq], w1 = u.WvS[cp][dq+1];
            float w2 = u.WvS[cp][dq+2], w3 = u.WvS[cp][dq+3];
            a4[0][0] += s0*w0; a4[0][1] += s0*w1; a4[0][2] += s0*w2; a4[0][3] += s0*w3;
            a4[1][0] += s1*w0; a4[1][1] += s1*w1; a4[1][2] += s1*w2; a4[1][3] += s1*w3;
            a4[2][0] += s2*w0; a4[2][1] += s2*w1; a4[2][2] += s2*w2; a4[2][3] += s2*w3;
        }
        #pragma unroll
        for (int j = 0; j < 4; j++) {
            const size_t rowo = ((size_t)b * DIM + dp + dq + j) * DIM + h * CH + ci;
            #pragma unroll
            for (int i = 0; i < 3; i++) {
                __half hh, ll;
                split1(a4[i][j], hh, ll);
                g_mth[rowo + i] = hh;
                g_mtl[rowo + i] = ll;
            }
        }
        __syncthreads();
    }
}

// ---------------------------------------------------------------------------
extern "C" void kernel_launch(void* const* d_in, const int* in_sizes, int n_in,
                              void* d_out, int out_size) {
    const float* x      = (const float*)d_in[0];
    const float* qkv_w  = (const float*)d_in[1];
    const float* temp   = (const float*)d_in[2];
    const float* proj_w = (const float*)d_in[3];
    const float* proj_b = (const float*)d_in[4];
    float* y = (float*)d_out;

    __half *xh, *xl, *xth, *xtl, *wqh, *wql, *pwh, *pwl;
    __half *Gh, *Gl, *mth, *mtl, *rh, *rl;
    float *Gbig, *tu;
    cudaGetSymbolAddress((void**)&xh, g_xh);
    cudaGetSymbolAddress((void**)&xl, g_xl);
    cudaGetSymbolAddress((void**)&xth, g_xth);
    cudaGetSymbolAddress((void**)&xtl, g_xtl);
    cudaGetSymbolAddress((void**)&wqh, g_wqh);
    cudaGetSymbolAddress((void**)&wql, g_wql);
    cudaGetSymbolAddress((void**)&pwh, g_pwh);
    cudaGetSymbolAddress((void**)&pwl, g_pwl);
    cudaGetSymbolAddress((void**)&Gbig, g_Gbig);
    cudaGetSymbolAddress((void**)&Gh, g_Gh);
    cudaGetSymbolAddress((void**)&Gl, g_Gl);
    cudaGetSymbolAddress((void**)&tu, g_tu);
    cudaGetSymbolAddress((void**)&mth, g_mth);
    cudaGetSymbolAddress((void**)&mtl, g_mtl);
    cudaGetSymbolAddress((void**)&rh, g_rh);
    cudaGetSymbolAddress((void**)&rl, g_rl);

    const size_t sX  = (size_t)NT * DIM;
    const size_t sXT = (size_t)DIM * NT;
    const size_t sG  = (size_t)DIM * DIM;

    cudaFuncSetAttribute(gemm5<0, 1>, cudaFuncAttributeMaxDynamicSharedMemorySize,
                         GSMEM);
    cudaFuncSetAttribute(gemm5<0, 0>, cudaFuncAttributeMaxDynamicSharedMemorySize,
                         GSMEM);
    cudaFuncSetAttribute(gemm5<1, 0>, cudaFuncAttributeMaxDynamicSharedMemorySize,
                         GSMEM);
    cudaFuncSetAttribute(gemm5<2, 0>, cudaFuncAttributeMaxDynamicSharedMemorySize,
                         GSMEM);

    // converts (x hi/lo + x^T hi/lo fused into one pass over x)
    transpose_split<<<dim3(NT / 32, DIM / 32, NB), 256>>>(x);
    conv_split<<<432, 256>>>((const float4*)qkv_w, (uint2*)wqh, (uint2*)wql,
                             3 * DIM * DIM / 4);
    conv_split<<<144, 256>>>((const float4*)proj_w, (uint2*)pwh, (uint2*)pwl,
                             DIM * DIM / 4);

    // G = x^T x  (K-split in halves of 1568)
    gemm5<0, 1><<<dim3(3, 3, 64), 256, GSMEM>>>(xth, xtl, xth, xtl,
        NT, NT, sXT, sXT, 98, 1568, Gbig, sG, DIM,
        nullptr, nullptr, nullptr, nullptr);
    conv_sum<<<(NB * DIM * DIM / 4 + 255) / 256, 256>>>((uint2*)Gh, (uint2*)Gl);

    // [T;U] = [Wq;Wk] * G
    gemm5<0, 0><<<dim3(3, 6, 32), 256, GSMEM>>>(wqh, wql, Gh, Gl,
        DIM, DIM, 0, sG, 24, 0, tu, 2 * sG, DIM,
        nullptr, nullptr, nullptr, nullptr);

    // scores + softmax + M^T
    scores_kernel<<<NB * NH, 256>>>(qkv_w, temp);

    // R = P * M  (via B = M^T)
    gemm5<1, 0><<<dim3(3, 3, 32), 256, GSMEM>>>(pwh, pwl, mth, mtl,
        DIM, DIM, 0, sG, 24, 0, nullptr, sG, DIM,
        rh, rl, nullptr, nullptr);

    // y = x R^T + bias  (A = R rows e, B = x rows token; transposed store)
    gemm5<2, 0><<<dim3(25, 3, 32), 256, GSMEM>>>(rh, rl, xh, xl,
        DIM, DIM, sG, sX, 24, 0, nullptr, 0, 0,
        nullptr, nullptr, proj_b, y);
}